// round 1
// baseline (speedup 1.0000x reference)
#include <cuda_runtime.h>
#include <math.h>

#define HID 128
#define BM  64      // edges per block tile
#define BN  128     // output cols (= HID)
#define BK  8       // K chunk
#define NPB 32      // nodes per block in embedding kernel

#define N_NODES_MAX 100000

// scratch: node embeddings [N, 128] fp32  (~51.2 MB, static device array — allowed)
__device__ float g_node_emb[N_NODES_MAX * HID];

// packed fp32x2 FMA (Blackwell): d = a*b + c on both lanes
__device__ __forceinline__ float2 ffma2(float2 a, float2 b, float2 c) {
    unsigned long long ua = *reinterpret_cast<unsigned long long*>(&a);
    unsigned long long ub = *reinterpret_cast<unsigned long long*>(&b);
    unsigned long long uc = *reinterpret_cast<unsigned long long*>(&c);
    unsigned long long ud;
    asm("fma.rn.f32x2 %0, %1, %2, %3;" : "=l"(ud) : "l"(ua), "l"(ub), "l"(uc));
    return *reinterpret_cast<float2*>(&ud);
}

__device__ __forceinline__ float silu(float v) {
    return v / (1.0f + expf(-v));
}

// ---------------------------------------------------------------------------
// Kernel 0: node_emb[n,j] = (x @ Wa + ba + pos @ Wp + bp)[n,j]
// 128 threads = one column each; weights live in registers; NPB nodes/block.
// ---------------------------------------------------------------------------
__global__ void node_emb_kernel(const float* __restrict__ x,
                                const float* __restrict__ pos,
                                const float* __restrict__ Wa,
                                const float* __restrict__ ba,
                                const float* __restrict__ Wp,
                                const float* __restrict__ bp,
                                int N) {
    int j = threadIdx.x;  // 0..127
    float wa[16];
#pragma unroll
    for (int k = 0; k < 16; k++) wa[k] = Wa[k * HID + j];
    float wp[3];
#pragma unroll
    for (int k = 0; k < 3; k++) wp[k] = Wp[k * HID + j];
    float bb = ba[j] + bp[j];

    __shared__ float xs[NPB][16];
    __shared__ float ps[NPB][3];
    int n0 = blockIdx.x * NPB;

    for (int i = j; i < NPB * 16; i += 128) {
        int n = n0 + (i >> 4);
        xs[i >> 4][i & 15] = (n < N) ? x[n * 16 + (i & 15)] : 0.0f;
    }
    for (int i = j; i < NPB * 3; i += 128) {
        int n = n0 + i / 3;
        ps[i / 3][i % 3] = (n < N) ? pos[n * 3 + i % 3] : 0.0f;
    }
    __syncthreads();

    for (int n = 0; n < NPB; n++) {
        if (n0 + n >= N) break;
        float s = bb;
#pragma unroll
        for (int k = 0; k < 16; k++) s += xs[n][k] * wa[k];
#pragma unroll
        for (int k = 0; k < 3; k++) s += ps[n][k] * wp[k];
        g_node_emb[(n0 + n) * HID + j] = s;
    }
}

// ---------------------------------------------------------------------------
// Kernel 1: fused edge MLP.
// Per block: 64 edges. GEMM1 (K=257, gathered A), silu, GEMM2 (K=128), silu,
// GEMM3 (N=4). h tiles stay in a swizzled smem buffer; never touch HBM.
// Thread map: 256 threads = 16x16; each owns 4 rows x 8 cols (4x4 float2 acc).
// ---------------------------------------------------------------------------
__global__ void __launch_bounds__(256)
edge_mlp_kernel(const float* __restrict__ pos,
                const int* __restrict__ ei,       // [2, E]
                const float* __restrict__ W1, const float* __restrict__ b1,
                const float* __restrict__ W2, const float* __restrict__ b2,
                const float* __restrict__ W3, const float* __restrict__ b3,
                float* __restrict__ out, int E) {
    __shared__ __align__(16) float As[BK * BM];    // [k][row]
    __shared__ __align__(16) float Bs[BK * BN];    // [k][col]
    __shared__ __align__(16) float hs[HID * BM];   // [col][row], XOR-swizzled rows
    __shared__ int   s_src[BM];
    __shared__ int   s_dst[BM];
    __shared__ float s_dist[BM];
    __shared__ float w3s[HID * 4];
    __shared__ float b3s[4];

    const int tid = threadIdx.x;
    const int tx = tid & 15;       // col group
    const int ty = tid >> 4;       // row group
    const int tile0 = blockIdx.x * BM;
    const int* __restrict__ srcp = ei;
    const int* __restrict__ dstp = ei + E;

    // ---- setup: indices, distances, W3 ----
    if (tid < BM) {
        int ge = tile0 + tid;
        if (ge >= E) ge = E - 1;
        int s = srcp[ge], d = dstp[ge];
        s_src[tid] = s * HID;
        s_dst[tid] = d * HID;
        float dx = pos[s * 3 + 0] - pos[d * 3 + 0];
        float dy = pos[s * 3 + 1] - pos[d * 3 + 1];
        float dz = pos[s * 3 + 2] - pos[d * 3 + 2];
        s_dist[tid] = sqrtf(dx * dx + dy * dy + dz * dz);
    }
    for (int i = tid; i < HID * 4; i += 256) w3s[i] = W3[i];
    if (tid < 4) b3s[tid] = b3[tid];
    __syncthreads();

    float2 acc[4][4];
#pragma unroll
    for (int i = 0; i < 4; i++)
#pragma unroll
        for (int jj = 0; jj < 4; jj++) acc[i][jj] = make_float2(0.0f, 0.0f);

    // A-gather mapping: thread -> (row = tid&63, k-pair index = tid>>6)
    const int arow = tid & 63;
    const int khalf = tid >> 6;    // 0..3 -> k offsets 0,2,4,6

    // ================= GEMM1: edge_input[:,0:256] @ W1[0:256,:] =============
    for (int kb = 0; kb < 2 * HID; kb += BK) {
        int k0 = kb + khalf * 2;
        const float* gbase = (k0 < HID)
            ? (g_node_emb + s_src[arow] + k0)
            : (g_node_emb + s_dst[arow] + (k0 - HID));
        float2 av = *reinterpret_cast<const float2*>(gbase);
        float4 bv = *reinterpret_cast<const float4*>(
            &W1[(kb + (tid >> 5)) * HID + ((tid & 31) << 2)]);

        __syncthreads();   // previous chunk's smem reads complete
        As[(khalf * 2 + 0) * BM + arow] = av.x;
        As[(khalf * 2 + 1) * BM + arow] = av.y;
        *reinterpret_cast<float4*>(&Bs[(tid >> 5) * BN + ((tid & 31) << 2)]) = bv;
        __syncthreads();

#pragma unroll
        for (int kk = 0; kk < BK; kk++) {
            float4 a  = *reinterpret_cast<const float4*>(&As[kk * BM + ty * 4]);
            float4 bA = *reinterpret_cast<const float4*>(&Bs[kk * BN + tx * 8]);
            float4 bB = *reinterpret_cast<const float4*>(&Bs[kk * BN + tx * 8 + 4]);
            float2 bp2[4] = {{bA.x, bA.y}, {bA.z, bA.w}, {bB.x, bB.y}, {bB.z, bB.w}};
            float  ar[4]  = {a.x, a.y, a.z, a.w};
#pragma unroll
            for (int i = 0; i < 4; i++) {
                float2 ap = {ar[i], ar[i]};
#pragma unroll
                for (int jj = 0; jj < 4; jj++)
                    acc[i][jj] = ffma2(ap, bp2[jj], acc[i][jj]);
            }
        }
    }

    // ---- GEMM1 epilogue: + dist * W1[256,:] + b1, silu, store h1 to hs ----
    {
        float2 w256[4], bb1[4];
#pragma unroll
        for (int jj = 0; jj < 4; jj++) {
            int col = tx * 8 + jj * 2;
            w256[jj] = *reinterpret_cast<const float2*>(&W1[2 * HID * HID + col]);
            bb1[jj]  = *reinterpret_cast<const float2*>(&b1[col]);
        }
        const int sw = (tx & 7) << 2;   // ((col>>3)&7)<<2, col>>3 == tx here
#pragma unroll
        for (int i = 0; i < 4; i++) {
            int row = ty * 4 + i;
            float dd = s_dist[row];
            float2 dp = {dd, dd};
#pragma unroll
            for (int jj = 0; jj < 4; jj++) {
                float2 v = ffma2(dp, w256[jj], acc[i][jj]);
                v.x = silu(v.x + bb1[jj].x);
                v.y = silu(v.y + bb1[jj].y);
                int col = tx * 8 + jj * 2;
                hs[col * BM + (row ^ sw)]       = v.x;
                hs[(col + 1) * BM + (row ^ sw)] = v.y;
                acc[i][jj] = make_float2(0.0f, 0.0f);
            }
        }
    }
    __syncthreads();   // h1 visible

    // ================= GEMM2: h1 @ W2 =======================================
    for (int kb = 0; kb < HID; kb += BK) {
        float4 bv = *reinterpret_cast<const float4*>(
            &W2[(kb + (tid >> 5)) * HID + ((tid & 31) << 2)]);
        __syncthreads();
        *reinterpret_cast<float4*>(&Bs[(tid >> 5) * BN + ((tid & 31) << 2)]) = bv;
        __syncthreads();

#pragma unroll
        for (int kk = 0; kk < BK; kk++) {
            int k = kb + kk;
            int sw = ((k >> 3) & 7) << 2;
            float4 a  = *reinterpret_cast<const float4*>(&hs[k * BM + ((ty * 4) ^ sw)]);
            float4 bA = *reinterpret_cast<const float4*>(&Bs[kk * BN + tx * 8]);
            float4 bB = *reinterpret_cast<const float4*>(&Bs[kk * BN + tx * 8 + 4]);
            float2 bp2[4] = {{bA.x, bA.y}, {bA.z, bA.w}, {bB.x, bB.y}, {bB.z, bB.w}};
            float  ar[4]  = {a.x, a.y, a.z, a.w};
#pragma unroll
            for (int i = 0; i < 4; i++) {
                float2 ap = {ar[i], ar[i]};
#pragma unroll
                for (int jj = 0; jj < 4; jj++)
                    acc[i][jj] = ffma2(ap, bp2[jj], acc[i][jj]);
            }
        }
    }

    // ---- GEMM2 epilogue: + b2, silu, store h2 to hs (overwrite) ----
    __syncthreads();   // all hs reads done before overwrite
    {
        const int sw = (tx & 7) << 2;
#pragma unroll
        for (int i = 0; i < 4; i++) {
            int row = ty * 4 + i;
#pragma unroll
            for (int jj = 0; jj < 4; jj++) {
                int col = tx * 8 + jj * 2;
                float2 bb2 = *reinterpret_cast<const float2*>(&b2[col]);
                float2 v = acc[i][jj];
                v.x = silu(v.x + bb2.x);
                v.y = silu(v.y + bb2.y);
                hs[col * BM + (row ^ sw)]       = v.x;
                hs[(col + 1) * BM + (row ^ sw)] = v.y;
            }
        }
    }
    __syncthreads();

    // ================= GEMM3: h2 @ W3 + b3  (N=4) ===========================
    {
        int e = tid >> 2;   // 0..63
        int c = tid & 3;    // 0..3
        float sum = b3s[c];
#pragma unroll 8
        for (int k = 0; k < HID; k++) {
            int sw = ((k >> 3) & 7) << 2;
            sum += hs[k * BM + (e ^ sw)] * w3s[k * 4 + c];
        }
        if (tile0 + e < E) out[(tile0 + e) * 4 + c] = sum;
    }
}

// ---------------------------------------------------------------------------
extern "C" void kernel_launch(void* const* d_in, const int* in_sizes, int n_in,
                              void* d_out, int out_size) {
    const float* x   = (const float*)d_in[0];
    const float* pos = (const float*)d_in[1];
    const int*   ei  = (const int*)  d_in[2];
    const float* Wa  = (const float*)d_in[3];
    const float* ba  = (const float*)d_in[4];
    const float* Wp  = (const float*)d_in[5];
    const float* bp  = (const float*)d_in[6];
    const float* W1  = (const float*)d_in[7];
    const float* b1  = (const float*)d_in[8];
    const float* W2  = (const float*)d_in[9];
    const float* b2  = (const float*)d_in[10];
    const float* W3  = (const float*)d_in[11];
    const float* b3  = (const float*)d_in[12];
    float* out = (float*)d_out;

    int N = in_sizes[0] / 16;     // ATOM_DIM = 16
    int E = in_sizes[2] / 2;      // edge_index [2, E]

    node_emb_kernel<<<(N + NPB - 1) / NPB, 128>>>(x, pos, Wa, ba, Wp, bp, N);
    edge_mlp_kernel<<<(E + BM - 1) / BM, 256>>>(pos, ei, W1, b1, W2, b2, W3, b3,
                                                out, E);
}

// round 2
// speedup vs baseline: 2.1238x; 2.1238x over previous
#include <cuda_runtime.h>
#include <math.h>

#define HID 128
#define BM  128     // edges per block tile
#define BK  8       // K chunk
#define NPB 32
#define N_NODES_MAX 100000

// node embeddings scratch [N, 128] fp32 (~51 MB static device array)
__device__ float g_node_emb[N_NODES_MAX * HID];

// packed fp32x2 FMA (Blackwell)
__device__ __forceinline__ float2 ffma2(float2 a, float2 b, float2 c) {
    unsigned long long ua = *reinterpret_cast<unsigned long long*>(&a);
    unsigned long long ub = *reinterpret_cast<unsigned long long*>(&b);
    unsigned long long uc = *reinterpret_cast<unsigned long long*>(&c);
    unsigned long long ud;
    asm("fma.rn.f32x2 %0, %1, %2, %3;" : "=l"(ud) : "l"(ua), "l"(ub), "l"(uc));
    return *reinterpret_cast<float2*>(&ud);
}

__device__ __forceinline__ float silu(float v) {
    return __fdividef(v, 1.0f + __expf(-v));
}

// ---------------------------------------------------------------------------
// Kernel 0: node_emb = x@Wa + ba + pos@Wp + bp
// ---------------------------------------------------------------------------
__global__ void node_emb_kernel(const float* __restrict__ x,
                                const float* __restrict__ pos,
                                const float* __restrict__ Wa,
                                const float* __restrict__ ba,
                                const float* __restrict__ Wp,
                                const float* __restrict__ bp,
                                int N) {
    int j = threadIdx.x;  // 0..127
    float wa[16];
#pragma unroll
    for (int k = 0; k < 16; k++) wa[k] = Wa[k * HID + j];
    float wp[3];
#pragma unroll
    for (int k = 0; k < 3; k++) wp[k] = Wp[k * HID + j];
    float bb = ba[j] + bp[j];

    __shared__ float xs[NPB][16];
    __shared__ float ps[NPB][3];
    int n0 = blockIdx.x * NPB;

    for (int i = j; i < NPB * 16; i += 128) {
        int n = n0 + (i >> 4);
        xs[i >> 4][i & 15] = (n < N) ? x[n * 16 + (i & 15)] : 0.0f;
    }
    for (int i = j; i < NPB * 3; i += 128) {
        int n = n0 + i / 3;
        ps[i / 3][i % 3] = (n < N) ? pos[n * 3 + i % 3] : 0.0f;
    }
    __syncthreads();

    for (int n = 0; n < NPB; n++) {
        if (n0 + n >= N) break;
        float s = bb;
#pragma unroll
        for (int k = 0; k < 16; k++) s += xs[n][k] * wa[k];
#pragma unroll
        for (int k = 0; k < 3; k++) s += ps[n][k] * wp[k];
        g_node_emb[(n0 + n) * HID + j] = s;
    }
}

// ---------------------------------------------------------------------------
// Kernel 1: fused edge MLP. 128 edges/block, 256 threads, 8x8 micro-tiles.
// Ping-pong smem, one sync per K-chunk. h stays in swizzled smem.
// ---------------------------------------------------------------------------
__global__ void __launch_bounds__(256, 2)
edge_mlp_kernel(const float* __restrict__ pos,
                const int* __restrict__ ei,
                const float* __restrict__ W1, const float* __restrict__ b1,
                const float* __restrict__ W2, const float* __restrict__ b2,
                const float* __restrict__ W3, const float* __restrict__ b3,
                float* __restrict__ out, int E) {
    extern __shared__ __align__(16) float sm[];
    float* As    = sm;                       // [2][BK*BM]   = 2*1024
    float* Bs    = sm + 2 * BK * BM;         // [2][BK*HID]  = 2*1024
    float* hs    = Bs + 2 * BK * HID;        // [HID*BM]     = 16384
    int*   s_src = (int*)(hs + HID * BM);    // 128
    int*   s_dst = s_src + BM;               // 128
    float* s_dist = (float*)(s_dst + BM);    // 128
    float* w3s   = s_dist + BM;              // 512
    float* b3s   = w3s + HID * 4;            // 4

    const int tid = threadIdx.x;
    const int tx = tid & 15;        // col group 0..15
    const int ty = tid >> 4;        // row group 0..15
    const int tile0 = blockIdx.x * BM;
    const int* __restrict__ srcp = ei;
    const int* __restrict__ dstp = ei + E;

    // ---- setup ----
    if (tid < BM) {
        int ge = tile0 + tid;
        if (ge >= E) ge = E - 1;
        int s = srcp[ge], d = dstp[ge];
        s_src[tid] = s * HID;
        s_dst[tid] = d * HID;
        float dx = pos[s * 3 + 0] - pos[d * 3 + 0];
        float dy = pos[s * 3 + 1] - pos[d * 3 + 1];
        float dz = pos[s * 3 + 2] - pos[d * 3 + 2];
        s_dist[tid] = sqrtf(dx * dx + dy * dy + dz * dz);
    }
    for (int i = tid; i < HID * 4; i += 256) w3s[i] = W3[i];
    if (tid < 4) b3s[tid] = b3[tid];
    __syncthreads();

    const int grow = tid & 127;              // gather row
    const int gk   = (tid >> 7) << 2;        // 0 or 4
    const int srcOff = s_src[grow];
    const int dstOff = s_dst[grow];
    const int r0 = ty * 8;                   // thread's row base
    const int cA = tx * 4;                   // col group A
    const int cB = 64 + tx * 4;              // col group B
    const int brow = tid >> 5;               // 0..7 (B staging row)
    const int bcol = (tid & 31) << 2;        // 0..124 (B staging col)

    float2 acc[8][4];
#pragma unroll
    for (int i = 0; i < 8; i++)
#pragma unroll
        for (int j = 0; j < 4; j++) acc[i][j] = make_float2(0.f, 0.f);

    // ---- GEMM1 prologue: stage chunk 0 ----
    {
        float4 a = *reinterpret_cast<const float4*>(&g_node_emb[srcOff + gk]);
        float4 b = *reinterpret_cast<const float4*>(&W1[brow * HID + bcol]);
        As[(gk + 0) * BM + grow] = a.x;
        As[(gk + 1) * BM + grow] = a.y;
        As[(gk + 2) * BM + grow] = a.z;
        As[(gk + 3) * BM + grow] = a.w;
        *reinterpret_cast<float4*>(&Bs[brow * HID + bcol]) = b;
    }
    __syncthreads();

    // ================= GEMM1: K = 256 (gathered A) =====================
    int p = 0;
    for (int kb = 0; kb < 2 * HID; kb += BK) {
        float4 an, bn;
        const bool has_next = (kb + BK) < 2 * HID;
        if (has_next) {
            int k0 = kb + BK + gk;
            const float* gb = (k0 < HID) ? &g_node_emb[srcOff + k0]
                                         : &g_node_emb[dstOff + k0 - HID];
            an = *reinterpret_cast<const float4*>(gb);
            bn = *reinterpret_cast<const float4*>(&W1[(kb + BK + brow) * HID + bcol]);
        }
        const float* Ap = As + p * (BK * BM);
        const float* Bp = Bs + p * (BK * HID);
#pragma unroll
        for (int kk = 0; kk < BK; kk++) {
            float4 a0  = *reinterpret_cast<const float4*>(&Ap[kk * BM + r0]);
            float4 a1  = *reinterpret_cast<const float4*>(&Ap[kk * BM + r0 + 4]);
            float4 b0  = *reinterpret_cast<const float4*>(&Bp[kk * HID + cA]);
            float4 b1v = *reinterpret_cast<const float4*>(&Bp[kk * HID + cB]);
            float  ar[8]  = {a0.x, a0.y, a0.z, a0.w, a1.x, a1.y, a1.z, a1.w};
            float2 bp2[4] = {{b0.x, b0.y}, {b0.z, b0.w}, {b1v.x, b1v.y}, {b1v.z, b1v.w}};
#pragma unroll
            for (int i = 0; i < 8; i++) {
                float2 ap = make_float2(ar[i], ar[i]);
#pragma unroll
                for (int j = 0; j < 4; j++) acc[i][j] = ffma2(ap, bp2[j], acc[i][j]);
            }
        }
        if (has_next) {
            float* Ad = As + (p ^ 1) * (BK * BM);
            float* Bd = Bs + (p ^ 1) * (BK * HID);
            Ad[(gk + 0) * BM + grow] = an.x;
            Ad[(gk + 1) * BM + grow] = an.y;
            Ad[(gk + 2) * BM + grow] = an.z;
            Ad[(gk + 3) * BM + grow] = an.w;
            *reinterpret_cast<float4*>(&Bd[brow * HID + bcol]) = bn;
            __syncthreads();
            p ^= 1;
        }
    }

    // ---- GEMM1 epilogue: + dist*W1[256,:] + b1, silu, swizzled store ----
    {
        float4 wA = *reinterpret_cast<const float4*>(&W1[2 * HID * HID + cA]);
        float4 wB = *reinterpret_cast<const float4*>(&W1[2 * HID * HID + cB]);
        float4 bA = *reinterpret_cast<const float4*>(&b1[cA]);
        float4 bB = *reinterpret_cast<const float4*>(&b1[cB]);
        float2 wv[4] = {{wA.x, wA.y}, {wA.z, wA.w}, {wB.x, wB.y}, {wB.z, wB.w}};
        float  bv[8] = {bA.x, bA.y, bA.z, bA.w, bB.x, bB.y, bB.z, bB.w};
#pragma unroll
        for (int i = 0; i < 8; i++) {
            float dd = s_dist[r0 + i];
            float2 dp = make_float2(dd, dd);
#pragma unroll
            for (int j = 0; j < 4; j++) {
                float2 v = ffma2(dp, wv[j], acc[i][j]);
                v.x = silu(v.x + bv[2 * j]);
                v.y = silu(v.y + bv[2 * j + 1]);
                acc[i][j] = v;
            }
        }
#pragma unroll
        for (int jc = 0; jc < 8; jc++) {
            int col = (jc < 4) ? (cA + jc) : (cB + jc - 4);
            int swz = ((col >> 2) & 7) << 2;
            float4 vlo, vhi;
            vlo.x = (jc & 1) ? acc[0][jc >> 1].y : acc[0][jc >> 1].x;
            vlo.y = (jc & 1) ? acc[1][jc >> 1].y : acc[1][jc >> 1].x;
            vlo.z = (jc & 1) ? acc[2][jc >> 1].y : acc[2][jc >> 1].x;
            vlo.w = (jc & 1) ? acc[3][jc >> 1].y : acc[3][jc >> 1].x;
            vhi.x = (jc & 1) ? acc[4][jc >> 1].y : acc[4][jc >> 1].x;
            vhi.y = (jc & 1) ? acc[5][jc >> 1].y : acc[5][jc >> 1].x;
            vhi.z = (jc & 1) ? acc[6][jc >> 1].y : acc[6][jc >> 1].x;
            vhi.w = (jc & 1) ? acc[7][jc >> 1].y : acc[7][jc >> 1].x;
            *reinterpret_cast<float4*>(&hs[col * BM + (r0 ^ swz)]) = vlo;
            *reinterpret_cast<float4*>(&hs[col * BM + ((r0 + 4) ^ swz)]) = vhi;
        }
    }

    // reset acc + stage W2 chunk 0
#pragma unroll
    for (int i = 0; i < 8; i++)
#pragma unroll
        for (int j = 0; j < 4; j++) acc[i][j] = make_float2(0.f, 0.f);
    {
        float4 b = *reinterpret_cast<const float4*>(&W2[brow * HID + bcol]);
        *reinterpret_cast<float4*>(&Bs[brow * HID + bcol]) = b;
    }
    __syncthreads();   // h1 + W2 chunk0 visible; all GEMM1 smem reads done

    // ================= GEMM2: h1 @ W2, K = 128 ========================
    int q = 0;
    for (int kb = 0; kb < HID; kb += BK) {
        float4 bn;
        const bool has_next = (kb + BK) < HID;
        if (has_next)
            bn = *reinterpret_cast<const float4*>(&W2[(kb + BK + brow) * HID + bcol]);
        const float* Bp = Bs + q * (BK * HID);
#pragma unroll
        for (int kk = 0; kk < BK; kk++) {
            int k = kb + kk;
            int swz = ((k >> 2) & 7) << 2;
            float4 a0  = *reinterpret_cast<const float4*>(&hs[k * BM + (r0 ^ swz)]);
            float4 a1  = *reinterpret_cast<const float4*>(&hs[k * BM + ((r0 + 4) ^ swz)]);
            float4 b0  = *reinterpret_cast<const float4*>(&Bp[kk * HID + cA]);
            float4 b1v = *reinterpret_cast<const float4*>(&Bp[kk * HID + cB]);
            float  ar[8]  = {a0.x, a0.y, a0.z, a0.w, a1.x, a1.y, a1.z, a1.w};
            float2 bp2[4] = {{b0.x, b0.y}, {b0.z, b0.w}, {b1v.x, b1v.y}, {b1v.z, b1v.w}};
#pragma unroll
            for (int i = 0; i < 8; i++) {
                float2 ap = make_float2(ar[i], ar[i]);
#pragma unroll
                for (int j = 0; j < 4; j++) acc[i][j] = ffma2(ap, bp2[j], acc[i][j]);
            }
        }
        if (has_next) {
            *reinterpret_cast<float4*>(&Bs[(q ^ 1) * (BK * HID) + brow * HID + bcol]) = bn;
            __syncthreads();
            q ^= 1;
        }
    }
    __syncthreads();   // all hs reads complete before overwrite

    // ---- GEMM2 epilogue: + b2, silu, swizzled store (overwrite hs) ----
    {
        float4 bA = *reinterpret_cast<const float4*>(&b2[cA]);
        float4 bB = *reinterpret_cast<const float4*>(&b2[cB]);
        float bv[8] = {bA.x, bA.y, bA.z, bA.w, bB.x, bB.y, bB.z, bB.w};
#pragma unroll
        for (int i = 0; i < 8; i++) {
#pragma unroll
            for (int j = 0; j < 4; j++) {
                float2 v = acc[i][j];
                v.x = silu(v.x + bv[2 * j]);
                v.y = silu(v.y + bv[2 * j + 1]);
                acc[i][j] = v;
            }
        }
#pragma unroll
        for (int jc = 0; jc < 8; jc++) {
            int col = (jc < 4) ? (cA + jc) : (cB + jc - 4);
            int swz = ((col >> 2) & 7) << 2;
            float4 vlo, vhi;
            vlo.x = (jc & 1) ? acc[0][jc >> 1].y : acc[0][jc >> 1].x;
            vlo.y = (jc & 1) ? acc[1][jc >> 1].y : acc[1][jc >> 1].x;
            vlo.z = (jc & 1) ? acc[2][jc >> 1].y : acc[2][jc >> 1].x;
            vlo.w = (jc & 1) ? acc[3][jc >> 1].y : acc[3][jc >> 1].x;
            vhi.x = (jc & 1) ? acc[4][jc >> 1].y : acc[4][jc >> 1].x;
            vhi.y = (jc & 1) ? acc[5][jc >> 1].y : acc[5][jc >> 1].x;
            vhi.z = (jc & 1) ? acc[6][jc >> 1].y : acc[6][jc >> 1].x;
            vhi.w = (jc & 1) ? acc[7][jc >> 1].y : acc[7][jc >> 1].x;
            *reinterpret_cast<float4*>(&hs[col * BM + (r0 ^ swz)]) = vlo;
            *reinterpret_cast<float4*>(&hs[col * BM + ((r0 + 4) ^ swz)]) = vhi;
        }
    }
    __syncthreads();

    // ================= GEMM3: h2 @ W3 + b3 (N=4) ======================
    {
        int e  = tid >> 1;            // 0..127
        int c0 = (tid & 1) << 1;      // 0 or 2
        float s0 = b3s[c0], s1 = b3s[c0 + 1];
#pragma unroll 8
        for (int k = 0; k < HID; k++) {
            int swz = ((k >> 2) & 7) << 2;
            float h = hs[k * BM + (e ^ swz)];
            s0 += h * w3s[k * 4 + c0];
            s1 += h * w3s[k * 4 + c0 + 1];
        }
        int ge = tile0 + e;
        if (ge < E)
            *reinterpret_cast<float2*>(&out[ge * 4 + c0]) = make_float2(s0, s1);
    }
}

// ---------------------------------------------------------------------------
extern "C" void kernel_launch(void* const* d_in, const int* in_sizes, int n_in,
                              void* d_out, int out_size) {
    const float* x   = (const float*)d_in[0];
    const float* pos = (const float*)d_in[1];
    const int*   ei  = (const int*)  d_in[2];
    const float* Wa  = (const float*)d_in[3];
    const float* ba  = (const float*)d_in[4];
    const float* Wp  = (const float*)d_in[5];
    const float* bp  = (const float*)d_in[6];
    const float* W1  = (const float*)d_in[7];
    const float* b1  = (const float*)d_in[8];
    const float* W2  = (const float*)d_in[9];
    const float* b2  = (const float*)d_in[10];
    const float* W3  = (const float*)d_in[11];
    const float* b3  = (const float*)d_in[12];
    float* out = (float*)d_out;

    int N = in_sizes[0] / 16;
    int E = in_sizes[2] / 2;

    // dynamic smem: As(2048) + Bs(2048) + hs(16384) + src/dst/dist(384)
    //             + w3s(512) + b3s(4) floats
    size_t smem_bytes = (size_t)(2 * BK * BM + 2 * BK * HID + HID * BM +
                                 3 * BM + HID * 4 + 4) * sizeof(float);
    cudaFuncSetAttribute(edge_mlp_kernel,
                         cudaFuncAttributeMaxDynamicSharedMemorySize,
                         (int)smem_bytes);

    node_emb_kernel<<<(N + NPB - 1) / NPB, 128>>>(x, pos, Wa, ba, Wp, bp, N);
    edge_mlp_kernel<<<(E + BM - 1) / BM, 256, smem_bytes>>>(
        pos, ei, W1, b1, W2, b2, W3, b3, out, E);
}

// round 4
// speedup vs baseline: 3.8019x; 1.7901x over previous
#include <cuda_runtime.h>
#include <math.h>
#include <stdint.h>

#define HID 128
#define BM  256      // edges per block
#define THREADS 512
#define NPB 32
#define N_NODES_MAX 100000

__device__ float g_node_emb[N_NODES_MAX * HID];
__device__ float g_w1p[8 * 4096];   // W1 chunks, mma-layout, tf32-rounded
__device__ float g_w2p[4 * 4096];   // W2 chunks

__device__ __forceinline__ float tf32r(float v) {
    float o; asm("cvt.rna.tf32.f32 %0, %1;" : "=f"(o) : "f"(v)); return o;
}
__device__ __forceinline__ float silu(float v) {
    return __fdividef(v, 1.0f + __expf(-v));
}
__device__ __forceinline__ void mma8(float4& d,
                                     uint32_t a0, uint32_t a1, uint32_t a2, uint32_t a3,
                                     uint32_t b0, uint32_t b1) {
    asm volatile(
        "mma.sync.aligned.m16n8k8.row.col.f32.tf32.tf32.f32 "
        "{%0,%1,%2,%3},{%4,%5,%6,%7},{%8,%9},{%0,%1,%2,%3};"
        : "+f"(d.x), "+f"(d.y), "+f"(d.z), "+f"(d.w)
        : "r"(a0), "r"(a1), "r"(a2), "r"(a3), "r"(b0), "r"(b1));
}

// ------------------- Kernel A: node embeddings ------------------------------
__global__ void node_emb_kernel(const float* __restrict__ x,
                                const float* __restrict__ pos,
                                const float* __restrict__ Wa,
                                const float* __restrict__ ba,
                                const float* __restrict__ Wp,
                                const float* __restrict__ bp, int N) {
    int j = threadIdx.x;
    float wa[16];
#pragma unroll
    for (int k = 0; k < 16; k++) wa[k] = Wa[k * HID + j];
    float wp[3];
#pragma unroll
    for (int k = 0; k < 3; k++) wp[k] = Wp[k * HID + j];
    float bb = ba[j] + bp[j];

    __shared__ float xs[NPB][16];
    __shared__ float ps[NPB][3];
    int n0 = blockIdx.x * NPB;
    for (int i = j; i < NPB * 16; i += 128) {
        int n = n0 + (i >> 4);
        xs[i >> 4][i & 15] = (n < N) ? x[n * 16 + (i & 15)] : 0.0f;
    }
    for (int i = j; i < NPB * 3; i += 128) {
        int n = n0 + i / 3;
        ps[i / 3][i % 3] = (n < N) ? pos[n * 3 + i % 3] : 0.0f;
    }
    __syncthreads();
    for (int n = 0; n < NPB; n++) {
        if (n0 + n >= N) break;
        float s = bb;
#pragma unroll
        for (int k = 0; k < 16; k++) s += xs[n][k] * wa[k];
#pragma unroll
        for (int k = 0; k < 3; k++) s += ps[n][k] * wp[k];
        g_node_emb[(n0 + n) * HID + j] = s;
    }
}

// ------------- Kernel B: weight images in mma layout, tf32-rounded ---------
// layout per 32-k chunk (4096 floats): [kg2:2][n:128][16], pos = j*4+i where
// k_local_in_16 = i*4 + j.
__global__ void prep_weights(const float* __restrict__ W1,
                             const float* __restrict__ W2) {
    int c = blockIdx.x;                       // 0..7 -> W1, 8..11 -> W2
    const float* W = (c < 8) ? W1 : W2;
    int cc = (c < 8) ? c : c - 8;
    float* dst = (c < 8) ? (g_w1p + c * 4096) : (g_w2p + (c - 8) * 4096);
    for (int idx = threadIdx.x; idx < 4096; idx += 256) {
        int kg2 = idx >> 11;
        int rem = idx & 2047;
        int n = rem >> 4;
        int t = rem & 15;          // = j*4 + i
        int jj = t >> 2, ii = t & 3;
        int kl = kg2 * 16 + ii * 4 + jj;
        dst[idx] = tf32r(W[(cc * 32 + kl) * 128 + n]);
    }
}

// ------------------- Kernel C: fused edge MLP on mma.sync tf32 -------------
__global__ void __launch_bounds__(THREADS, 1)
edge_mlp_mma(const float* __restrict__ pos, const int* __restrict__ ei,
             const float* __restrict__ W1, const float* __restrict__ b1,
             const float* __restrict__ b2,
             const float* __restrict__ W3, const float* __restrict__ b3,
             float* __restrict__ out, int E) {
    extern __shared__ __align__(16) float sm[];
    float* X  = sm;               // 32768 floats: As[2] during GEMM1, hs after
    float* Y  = sm + 32768;       // 8192 floats: Bs[2]
    int*   s_soff = (int*)(sm + 40960);
    int*   s_doff = s_soff + 256;
    float* s_dist = (float*)(s_doff + 256);
    float* s_w256 = s_dist + 256;     // 128
    float* s_b1   = s_w256 + 128;     // 128
    float* s_b2   = s_b1 + 128;       // 128
    float* w3s    = s_b2 + 128;       // 512
    float* b3s    = w3s + 512;        // 4

    const int tid  = threadIdx.x;
    const int lane = tid & 31;
    const int wid  = tid >> 5;
    const int wr   = wid >> 2;            // 0..3
    const int wc   = wid & 3;             // 0..3
    const int m_warp = wr * 64;
    const int n_warp = wc * 32;
    const int tile0 = blockIdx.x * BM;

    // ---- setup ----
    if (tid < BM) {
        int ge = tile0 + tid; if (ge >= E) ge = E - 1;
        int s = ei[ge], d = ei[E + ge];
        s_soff[tid] = s * HID;
        s_doff[tid] = d * HID;
        float dx = pos[s * 3 + 0] - pos[d * 3 + 0];
        float dy = pos[s * 3 + 1] - pos[d * 3 + 1];
        float dz = pos[s * 3 + 2] - pos[d * 3 + 2];
        s_dist[tid] = sqrtf(dx * dx + dy * dy + dz * dz);
    }
    if (tid >= BM && tid < BM + 128) {
        int c = tid - BM;
        s_w256[c] = W1[256 * 128 + c];
        s_b1[c] = b1[c];
        s_b2[c] = b2[c];
    }
    for (int i = tid; i < 512; i += THREADS) w3s[i] = W3[i];
    if (tid < 4) b3s[tid] = b3[tid];
    __syncthreads();

    // gather mapping: row = tid&255, kg2 = tid>>8 (16 consecutive k each)
    const int grow = tid & 255;
    const int gkg2 = tid >> 8;
    const int gxo  = (grow >> 1) & 3;

    float4 acc[4][4];
#pragma unroll
    for (int i = 0; i < 4; i++)
#pragma unroll
        for (int j = 0; j < 4; j++) acc[i][j] = make_float4(0.f, 0.f, 0.f, 0.f);

    // A gather loader: returns 4 float4 (already transposed + tf32) for chunk c
    auto loadA = [&](int c, float4* v) {
        int kbase = (c < 4) ? (c * 32) : ((c - 4) * 32);
        const int* offs = (c < 4) ? s_soff : s_doff;
        const float* g = g_node_emb + offs[grow] + kbase + gkg2 * 16;
        float4 r0 = *reinterpret_cast<const float4*>(g + 0);
        float4 r1 = *reinterpret_cast<const float4*>(g + 4);
        float4 r2 = *reinterpret_cast<const float4*>(g + 8);
        float4 r3 = *reinterpret_cast<const float4*>(g + 12);
        // transpose: v[j] = (r0[j], r1[j], r2[j], r3[j])
        v[0] = make_float4(tf32r(r0.x), tf32r(r1.x), tf32r(r2.x), tf32r(r3.x));
        v[1] = make_float4(tf32r(r0.y), tf32r(r1.y), tf32r(r2.y), tf32r(r3.y));
        v[2] = make_float4(tf32r(r0.z), tf32r(r1.z), tf32r(r2.z), tf32r(r3.z));
        v[3] = make_float4(tf32r(r0.w), tf32r(r1.w), tf32r(r2.w), tf32r(r3.w));
    };
    auto storeA = [&](float* Ab, const float4* v) {
        float4* d4 = reinterpret_cast<float4*>(Ab + gkg2 * 4096 + grow * 16);
#pragma unroll
        for (int j = 0; j < 4; j++) d4[j ^ gxo] = v[j];
    };
    auto loadB = [&](const float* gsrc, float4* v) {
        const float4* s4 = reinterpret_cast<const float4*>(gsrc);
        v[0] = s4[tid * 2 + 0];
        v[1] = s4[tid * 2 + 1];
    };
    auto storeB = [&](float* Bb, const float4* v) {
        float4* d4 = reinterpret_cast<float4*>(Bb);
        d4[tid * 2 + 0] = v[0];
        d4[tid * 2 + 1] = v[1];
    };

    const int fxo = (lane & 3) ^ ((lane >> 3) & 3);  // A frag xor offset
    // one 32-k chunk of mma work
    auto compute_chunk = [&](const float* Ab, const float* Bb) {
#pragma unroll
        for (int kg2 = 0; kg2 < 2; kg2++) {
            const float4* A4 = reinterpret_cast<const float4*>(Ab + kg2 * 4096);
            const float4* B4 = reinterpret_cast<const float4*>(Bb + kg2 * 2048);
            float4 bv[4];
#pragma unroll
            for (int ni = 0; ni < 4; ni++) {
                int n = n_warp + ni * 8 + (lane >> 2);
                bv[ni] = B4[n * 4 + (lane & 3)];
            }
#pragma unroll
            for (int mi = 0; mi < 4; mi++) {
                int r = m_warp + mi * 16 + (lane >> 2);
                float4 vlo = A4[r * 4 + fxo];
                float4 vhi = A4[(r + 8) * 4 + fxo];
#pragma unroll
                for (int ni = 0; ni < 4; ni++) {
                    mma8(acc[mi][ni],
                         __float_as_uint(vlo.x), __float_as_uint(vhi.x),
                         __float_as_uint(vlo.y), __float_as_uint(vhi.y),
                         __float_as_uint(bv[ni].x), __float_as_uint(bv[ni].y));
                    mma8(acc[mi][ni],
                         __float_as_uint(vlo.z), __float_as_uint(vhi.z),
                         __float_as_uint(vlo.w), __float_as_uint(vhi.w),
                         __float_as_uint(bv[ni].z), __float_as_uint(bv[ni].w));
                }
            }
        }
    };

    // ================= GEMM1: K=256 (gathered A, W1) ========================
    {
        float4 av[4], bvv[2];
        loadA(0, av); loadB(g_w1p, bvv);
        storeA(X, av); storeB(Y, bvv);
    }
    __syncthreads();
    int p = 0;
#pragma unroll 1
    for (int c = 0; c < 8; c++) {
        float4 av[4], bvv[2];
        if (c < 7) { loadA(c + 1, av); loadB(g_w1p + (c + 1) * 4096, bvv); }
        compute_chunk(X + p * 8192, Y + p * 4096);
        if (c < 7) {
            storeA(X + (p ^ 1) * 8192, av);
            storeB(Y + (p ^ 1) * 4096, bvv);
            __syncthreads();
            p ^= 1;
        }
    }
    __syncthreads();   // GEMM1 done; X/Y free for hs / W2

    // ---- epilogue1: h1 = tf32(silu(D1 + dist*w256 + b1)) -> hs (X) --------
    {
        float4 bvv[2];
        loadB(g_w2p, bvv);   // prefetch W2 chunk 0
#pragma unroll
        for (int mi = 0; mi < 4; mi++) {
            int r = m_warp + mi * 16 + (lane >> 2);
            float d0 = s_dist[r], d1 = s_dist[r + 8];
#pragma unroll
            for (int ni = 0; ni < 4; ni++) {
                int c0 = n_warp + ni * 8 + ((lane & 3) << 1);
                float w0 = s_w256[c0], w1 = s_w256[c0 + 1];
                float bb0 = s_b1[c0], bb1 = s_b1[c0 + 1];
                float4 a = acc[mi][ni];
                float v0 = tf32r(silu(a.x + d0 * w0 + bb0));
                float v1 = tf32r(silu(a.y + d0 * w1 + bb1));
                float v2 = tf32r(silu(a.z + d1 * w0 + bb0));
                float v3 = tf32r(silu(a.w + d1 * w1 + bb1));
                // hs scatter: (m, kcol) -> chunk*8192 + kg2*4096 + m*16 + (j^xo)*4 + i
#pragma unroll
                for (int e = 0; e < 4; e++) {
                    int kc = c0 + (e & 1);
                    int m  = r + ((e >> 1) << 3);
                    float vv = (e == 0) ? v0 : (e == 1) ? v1 : (e == 2) ? v2 : v3;
                    int chunk = kc >> 5, kg2 = (kc >> 4) & 1, k16 = kc & 15;
                    int jj = k16 & 3, ii = k16 >> 2;
                    X[chunk * 8192 + kg2 * 4096 + m * 16 +
                      ((jj ^ ((m >> 1) & 3)) << 2) + ii] = vv;
                }
                acc[mi][ni] = make_float4(0.f, 0.f, 0.f, 0.f);
            }
        }
        storeB(Y, bvv);
    }
    __syncthreads();

    // ================= GEMM2: h1 @ W2, K=128 ================================
    int q = 0;
#pragma unroll 1
    for (int c = 0; c < 4; c++) {
        float4 bvv[2];
        if (c < 3) loadB(g_w2p + (c + 1) * 4096, bvv);
        compute_chunk(X + c * 8192, Y + q * 4096);
        if (c < 3) {
            storeB(Y + (q ^ 1) * 4096, bvv);
            __syncthreads();
            q ^= 1;
        }
    }
    __syncthreads();   // all hs reads done; X reusable for partials

    // ---- epilogue2: silu(D2+b2) -> GEMM3 partials -> smem reduce -----------
    // part[cid][row][4], cid = wc*4 + (lane&3), stride 1032 floats per cid
    {
        const int cid = wc * 4 + (lane & 3);
#pragma unroll
        for (int mi = 0; mi < 4; mi++) {
            int r = m_warp + mi * 16 + (lane >> 2);
            float4 plo = make_float4(0.f, 0.f, 0.f, 0.f);
            float4 phi = make_float4(0.f, 0.f, 0.f, 0.f);
#pragma unroll
            for (int ni = 0; ni < 4; ni++) {
                int c0 = n_warp + ni * 8 + ((lane & 3) << 1);
                float4 a = acc[mi][ni];
                float v0 = silu(a.x + s_b2[c0]);
                float v1 = silu(a.y + s_b2[c0 + 1]);
                float v2 = silu(a.z + s_b2[c0]);
                float v3 = silu(a.w + s_b2[c0 + 1]);
                float4 w0 = *reinterpret_cast<const float4*>(&w3s[c0 * 4]);
                float4 w1 = *reinterpret_cast<const float4*>(&w3s[(c0 + 1) * 4]);
                plo.x += v0 * w0.x + v1 * w1.x;
                plo.y += v0 * w0.y + v1 * w1.y;
                plo.z += v0 * w0.z + v1 * w1.z;
                plo.w += v0 * w0.w + v1 * w1.w;
                phi.x += v2 * w0.x + v3 * w1.x;
                phi.y += v2 * w0.y + v3 * w1.y;
                phi.z += v2 * w0.z + v3 * w1.z;
                phi.w += v2 * w0.w + v3 * w1.w;
            }
            *reinterpret_cast<float4*>(&X[cid * 1032 + r * 4]) = plo;
            *reinterpret_cast<float4*>(&X[cid * 1032 + (r + 8) * 4]) = phi;
        }
    }
    __syncthreads();
    if (tid < BM) {
        float4 o = make_float4(b3s[0], b3s[1], b3s[2], b3s[3]);
#pragma unroll
        for (int cid = 0; cid < 16; cid++) {
            float4 pv = *reinterpret_cast<const float4*>(&X[cid * 1032 + tid * 4]);
            o.x += pv.x; o.y += pv.y; o.z += pv.z; o.w += pv.w;
        }
        int ge = tile0 + tid;
        if (ge < E) *reinterpret_cast<float4*>(&out[ge * 4]) = o;
    }
}

// ---------------------------------------------------------------------------
extern "C" void kernel_launch(void* const* d_in, const int* in_sizes, int n_in,
                              void* d_out, int out_size) {
    const float* x   = (const float*)d_in[0];
    const float* pos = (const float*)d_in[1];
    const int*   ei  = (const int*)  d_in[2];
    const float* Wa  = (const float*)d_in[3];
    const float* ba  = (const float*)d_in[4];
    const float* Wp  = (const float*)d_in[5];
    const float* bp  = (const float*)d_in[6];
    const float* W1  = (const float*)d_in[7];
    const float* b1  = (const float*)d_in[8];
    const float* W2  = (const float*)d_in[9];
    const float* b2  = (const float*)d_in[10];
    const float* W3  = (const float*)d_in[11];
    const float* b3  = (const float*)d_in[12];
    float* out = (float*)d_out;

    int N = in_sizes[0] / 16;
    int E = in_sizes[2] / 2;

    // smem: X 32768 + Y 8192 + aux (256+256+256+128+128+128+512+4 = 1668)
    size_t smem_bytes = (size_t)(32768 + 8192 + 1668) * sizeof(float);
    cudaFuncSetAttribute(edge_mlp_mma,
                         cudaFuncAttributeMaxDynamicSharedMemorySize,
                         (int)smem_bytes);

    node_emb_kernel<<<(N + NPB - 1) / NPB, 128>>>(x, pos, Wa, ba, Wp, bp, N);
    prep_weights<<<12, 256>>>(W1, W2);
    edge_mlp_mma<<<(E + BM - 1) / BM, THREADS, smem_bytes>>>(
        pos, ei, W1, b1, b2, W3, b3, out, E);
}